// round 14
// baseline (speedup 1.0000x reference)
#include <cuda_runtime.h>
#include <cuda_bf16.h>
#include <cuda_fp16.h>
#include <cstdint>

// Problem constants
#define SS 8        // streams
#define II 64       // modulations per stream
#define MM 256      // features per stream
#define NTOK 16384  // batch

// Fused weights (fp16): W~_g[s] = Wg[:, :, 0:M] @ Wx[s]  -> [4][S][M][64]
// i/f/o gates (0,1,3) are pre-scaled by 0.5 for the sigmoid identity.
__device__ __half g_wf16[4][SS][MM][II];
// Fused biases:  b~_g[s,m] = bg + Wg_x@bx + Wg_h@h0   (i/f/o scaled by 0.5)
__device__ float g_bias[4][SS][MM];

// ---------------------------------------------------------------------------
// helpers
// ---------------------------------------------------------------------------
// hardware tanh (MUFU.TANH, sm_75+): 1 MUFU op, rel err ~2^-11
__device__ __forceinline__ float tanh_f(float x) {
    float y;
    asm("tanh.approx.f32 %0, %1;" : "=f"(y) : "f"(x));
    return y;
}
// sigmoid with pre-scaled argument: x already = 0.5*(acc+bias)
__device__ __forceinline__ float sigmoid_ps(float xhalf) {
    return fmaf(0.5f, tanh_f(xhalf), 0.5f);
}

// pack two fp32 into fp16x2 (a in low half, b in high half), as u32
__device__ __forceinline__ uint32_t pack_h2_u32(float a, float b) {
    uint32_t r;
    asm("cvt.rn.f16x2.f32 %0, %1, %2;" : "=r"(r) : "f"(b), "f"(a));
    return r;
}

__device__ __forceinline__ uint32_t smem_u32(const void* p) {
    uint32_t a;
    asm("{ .reg .u64 t; cvta.to.shared.u64 t, %1; cvt.u32.u64 %0, t; }"
        : "=r"(a) : "l"(p));
    return a;
}

__device__ __forceinline__ void ldsm4(uint32_t& r0, uint32_t& r1,
                                      uint32_t& r2, uint32_t& r3, uint32_t addr) {
    asm volatile("ldmatrix.sync.aligned.m8n8.x4.shared.b16 {%0,%1,%2,%3}, [%4];"
                 : "=r"(r0), "=r"(r1), "=r"(r2), "=r"(r3) : "r"(addr));
}
__device__ __forceinline__ void ldsm4t(uint32_t& r0, uint32_t& r1,
                                       uint32_t& r2, uint32_t& r3, uint32_t addr) {
    asm volatile("ldmatrix.sync.aligned.m8n8.x4.trans.shared.b16 {%0,%1,%2,%3}, [%4];"
                 : "=r"(r0), "=r"(r1), "=r"(r2), "=r"(r3) : "r"(addr));
}

__device__ __forceinline__ void mma16816(float* c, const uint32_t* a,
                                         uint32_t b0, uint32_t b1) {
    asm volatile(
        "mma.sync.aligned.m16n8k16.row.col.f32.f16.f16.f32 "
        "{%0,%1,%2,%3}, {%4,%5,%6,%7}, {%8,%9}, {%0,%1,%2,%3};"
        : "+f"(c[0]), "+f"(c[1]), "+f"(c[2]), "+f"(c[3])
        : "r"(a[0]), "r"(a[1]), "r"(a[2]), "r"(a[3]), "r"(b0), "r"(b1));
}

// swizzled smem byte offset for rows of 128B: XOR 16B-chunk by (row&7)
__device__ __forceinline__ uint32_t swz(uint32_t row, uint32_t colbyte) {
    return row * 128u + (colbyte ^ ((row & 7u) << 4));
}

// convert 8 consecutive fp32 at src to 4 packed fp16x2 words
__device__ __forceinline__ uint4 cvt8_f32_to_h2(const float* src) {
    float4 v0 = *reinterpret_cast<const float4*>(src);
    float4 v1 = *reinterpret_cast<const float4*>(src + 4);
    uint4 r;
    r.x = pack_h2_u32(v0.x, v0.y);
    r.y = pack_h2_u32(v0.z, v0.w);
    r.z = pack_h2_u32(v1.x, v1.y);
    r.w = pack_h2_u32(v1.z, v1.w);
    return r;
}

#define CP_ASYNC16(dst, gsrc) \
    asm volatile("cp.async.cg.shared.global [%0], [%1], 16;" \
                 :: "r"(dst), "l"(gsrc) : "memory")

#define MBAR_INIT(addr, cnt) \
    asm volatile("mbarrier.init.shared.b64 [%0], %1;" :: "r"(addr), "r"(cnt) : "memory")
#define MBAR_ARRIVE(addr) \
    asm volatile("mbarrier.arrive.shared.b64 _, [%0];" :: "r"(addr) : "memory")
#define CP_ASYNC_MBAR_ARRIVE_NOINC(addr) \
    asm volatile("cp.async.mbarrier.arrive.noinc.shared::cta.b64 [%0];" :: "r"(addr) : "memory")

#define MBAR_WAIT_PARITY(addr, par) do {                                        \
    uint32_t _mb = (addr);                                                      \
    uint32_t _pa = (par);                                                       \
    uint32_t _done;                                                             \
    asm volatile(                                                               \
        "{\n\t"                                                                 \
        ".reg .pred p;\n\t"                                                     \
        "mbarrier.try_wait.parity.acquire.cta.shared::cta.b64 p, [%1], %2;\n\t" \
        "selp.b32 %0, 1, 0, p;\n\t"                                             \
        "}" : "=r"(_done) : "r"(_mb), "r"(_pa) : "memory");                     \
    if (!_done) {                                                               \
        asm volatile(                                                           \
            "{\n\t"                                                             \
            ".reg .pred P1;\n\t"                                                \
            "WL_%=:\n\t"                                                        \
            "mbarrier.try_wait.parity.acquire.cta.shared::cta.b64 P1, [%0], %1, 0x989680;\n\t" \
            "@P1 bra.uni WD_%=;\n\t"                                            \
            "bra.uni WL_%=;\n\t"                                                \
            "WD_%=:\n\t"                                                        \
            "}" :: "r"(_mb), "r"(_pa) : "memory");                              \
    }                                                                           \
} while (0)

// ---------------------------------------------------------------------------
// Kernel 1: weight/bias fusion via tensor cores (same as R12, prescaled)
// grid = (S, 4 gates, 4 m-blocks of 64), block = 256 (8 warps), 2 CTAs/SM
// ---------------------------------------------------------------------------
#define PC_A   0u
#define PC_B   32768u
#define PC_RED 65536u
#define PC_SZ  66560u

__global__ __launch_bounds__(256, 2)
void precompute_kernel(const float* __restrict__ Wx, const float* __restrict__ bx,
                       const float* __restrict__ Wi, const float* __restrict__ bi,
                       const float* __restrict__ Wf, const float* __restrict__ bf,
                       const float* __restrict__ Wg, const float* __restrict__ bg,
                       const float* __restrict__ Wo, const float* __restrict__ bo,
                       const float* __restrict__ h0) {
    extern __shared__ char psm[];
    const uint32_t smb = smem_u32(psm);

    const int s    = blockIdx.x;
    const int gate = blockIdx.y;
    const int m0   = blockIdx.z * 64;
    const int tid  = threadIdx.x;

    const float* WG;
    const float* bG;
    switch (gate) {
        case 0:  WG = Wi; bG = bi; break;
        case 1:  WG = Wf; bG = bf; break;
        case 2:  WG = Wg; bG = bg; break;
        default: WG = Wo; bG = bo; break;
    }
    const float gsc = (gate == 2) ? 1.0f : 0.5f;

    // ---- stage A: Wg x-half rows m0..m0+63, fp32 -> fp16, 512B rows ----
    for (int idx = tid; idx < 2048; idx += 256) {  // 64 rows x 32 chunks
        int mm = idx >> 5, ck = idx & 31;
        const float* src = WG + (size_t)(s * 256 + m0 + mm) * 512 + ck * 8;
        uint4 v = cvt8_f32_to_h2(src);
        uint32_t off = (uint32_t)mm * 512u + (((uint32_t)ck * 16u) ^ (((uint32_t)mm & 7u) << 4));
        *reinterpret_cast<uint4*>(psm + PC_A + off) = v;
    }
    // ---- stage B: Wx[s] [k=256][i=64], fp32 -> fp16, SW128 rows ----
    for (int idx = tid; idx < 2048; idx += 256) {  // 256 rows x 8 chunks
        int k = idx >> 3, ck = idx & 7;
        const float* src = Wx + (size_t)s * 16384 + k * 64 + ck * 8;
        uint4 v = cvt8_f32_to_h2(src);
        *reinterpret_cast<uint4*>(psm + PC_B + swz((uint32_t)k, (uint32_t)ck * 16)) = v;
    }
    __syncthreads();

    // ---- mma: warp tile = 16 m x 32 i, K = 256 in 16 steps ----
    const int w    = tid >> 5;
    const int lane = tid & 31;
    const int wm   = w >> 1;   // m group (0..3)
    const int wi   = w & 1;    // i group (0..1): i base = wi*32
    const int lrow  = lane & 15;
    const int lhalf = lane >> 4;

    const uint32_t arow = (uint32_t)(wm * 16 + lrow);
    const uint32_t abase = smb + PC_A + arow * 512u;
    const uint32_t axor  = (arow & 7u) << 4;

    // trans-ldsm lane addressing for B ([k][i] storage -> [i][k] fragment)
    const uint32_t krow_off = (uint32_t)((lane & 7) + ((lane & 16) >> 1));  // +8 for lanes>=16
    const uint32_t ib_off   = (uint32_t)((lane & 8) << 1);                  // +16B for lanes&8

    float acc[4][4];
#pragma unroll
    for (int ng = 0; ng < 4; ng++) {
#pragma unroll
        for (int q = 0; q < 4; q++) {
            acc[ng][q] = 0.0f;
        }
    }

#pragma unroll
    for (int ks = 0; ks < 16; ks++) {
        uint32_t a[4];
        ldsm4(a[0], a[1], a[2], a[3],
              abase + ((((uint32_t)(ks * 2 + lhalf)) * 16u) ^ axor));
        uint32_t krow = (uint32_t)(ks * 16) + krow_off;
        uint32_t brow = smb + PC_B + krow * 128u;
        uint32_t bxor = (krow & 7u) << 4;
        uint32_t b0[4], b1[4];
        ldsm4t(b0[0], b0[1], b0[2], b0[3],
               brow + (((uint32_t)(wi * 64 + 0) + ib_off) ^ bxor));
        ldsm4t(b1[0], b1[1], b1[2], b1[3],
               brow + (((uint32_t)(wi * 64 + 32) + ib_off) ^ bxor));
        mma16816(acc[0], a, b0[0], b0[2]);  // i 0-7
        mma16816(acc[1], a, b0[1], b0[3]);  // i 8-15
        mma16816(acc[2], a, b1[0], b1[2]);  // i 16-23
        mma16816(acc[3], a, b1[1], b1[3]);  // i 24-31
    }

    // ---- store fused fp16 weights (with gate scale) ----
    {
        const int qrow = lane >> 2, qcol = lane & 3;
        const int mrow = m0 + wm * 16 + qrow;
#pragma unroll
        for (int ng = 0; ng < 4; ng++) {
            int icol = wi * 32 + ng * 8 + qcol * 2;
            *reinterpret_cast<uint32_t*>(&g_wf16[gate][s][mrow][icol]) =
                pack_h2_u32(gsc * acc[ng][0], gsc * acc[ng][1]);
            *reinterpret_cast<uint32_t*>(&g_wf16[gate][s][mrow + 8][icol]) =
                pack_h2_u32(gsc * acc[ng][2], gsc * acc[ng][3]);
        }
    }

    // ---- fused bias (fp32 exact): 4 partials of 128 k per output row ----
    {
        float* red = reinterpret_cast<float*>(psm + PC_RED);
        const int mm = tid & 63, part = tid >> 6;
        const float* row = WG + (size_t)(s * 256 + m0 + mm) * 512;
        float p = 0.0f;
        if (part < 2) {
            const float4* a = reinterpret_cast<const float4*>(row + part * 128);
            const float4* b = reinterpret_cast<const float4*>(bx + s * 256 + part * 128);
#pragma unroll 4
            for (int k = 0; k < 32; k++) {
                float4 av = a[k], bv = b[k];
                p += av.x * bv.x + av.y * bv.y + av.z * bv.z + av.w * bv.w;
            }
        } else {
            const float4* a = reinterpret_cast<const float4*>(row + 256 + (part - 2) * 128);
            const float4* b = reinterpret_cast<const float4*>(h0 + s * 256 + (part - 2) * 128);
#pragma unroll 4
            for (int k = 0; k < 32; k++) {
                float4 av = a[k], bv = b[k];
                p += av.x * bv.x + av.y * bv.y + av.z * bv.z + av.w * bv.w;
            }
        }
        red[part * 64 + mm] = p;
        __syncthreads();
        if (tid < 64) {
            float b = bG[s * 256 + m0 + tid] +
                red[tid] + red[64 + tid] + red[128 + tid] + red[192 + tid];
            g_bias[gate][s][m0 + tid] = gsc * b;
        }
    }
}

// ---------------------------------------------------------------------------
// Kernel 2: main LSTM step. 64-token CTAs for occupancy (3 CTAs/SM target)
// + wave smoothing. mma.sync fp16 1-pass, mbarrier-pipelined B, fp32 epilogue.
// grid = (token-tiles=256, 1, stream=8) = 2048 CTAs, block = 256 (8 warps)
// warp tile = 16 tokens x (4 gates x 16 m)  -> acc = 32 regs
// smem: A(8K) + 2 x B(16K) + bias(4K) + c0(1K) + mbarriers ~= 45.1KB
// ---------------------------------------------------------------------------
#define SM_AH   0u
#define SM_BB   8192u      // buffer p at SM_BB + p*16384
#define SM_BIAS 40960u     // 1024 floats
#define SM_C0   45056u     // 256 floats
#define SM_MB   46080u     // full0, full1, rd0, rd1 (8B each)
#define SM_SZ   46112u

__global__ __launch_bounds__(256, 3)
void lstm_mma_kernel(const float* __restrict__ mod,
                     const float* __restrict__ c0,
                     float* __restrict__ out) {
    extern __shared__ char sm[];
    char* smp = sm;
    const uint32_t smbase = smem_u32(sm);

    const int s   = blockIdx.z;
    const int n0  = blockIdx.x * 64;  // token base
    const int tid = threadIdx.x;

    const uint32_t mb_full[2] = {smbase + SM_MB, smbase + SM_MB + 8};
    const uint32_t mb_rd[2]   = {smbase + SM_MB + 16, smbase + SM_MB + 24};

    if (tid == 0) {
        MBAR_INIT(mb_full[0], 256);
        MBAR_INIT(mb_full[1], 256);
        MBAR_INIT(mb_rd[0], 256);
        MBAR_INIT(mb_rd[1], 256);
    }
    __syncthreads();

    // ---- kick off B[0] via cp.async into buffer 0, tracked by full[0] ----
    for (int c = tid; c < 1024; c += 256) {
        int r = c >> 3, ck = c & 7;
        int g = r >> 5, ml = r & 31;
        uint32_t off = swz((uint32_t)r, (uint32_t)ck * 16);
        CP_ASYNC16(smbase + SM_BB + off,
                   __cvta_generic_to_global(&g_wf16[g][s][ml][ck * 8]));
    }
    CP_ASYNC_MBAR_ARRIVE_NOINC(mb_full[0]);

    // ---- stage A (64 tokens): fp32 -> fp16, SW128 (overlaps B0 copy) ----
    for (int c = tid; c < 512; c += 256) {
        int row = c >> 3, ck = c & 7;  // 16B chunk = 8 fp16
        const float* src = mod + (size_t)(n0 + row) * (SS * II) + s * II + ck * 8;
        uint4 v = cvt8_f32_to_h2(src);
        uint32_t off = swz((uint32_t)row, (uint32_t)ck * 16);
        *reinterpret_cast<uint4*>(smp + SM_AH + off) = v;
    }

    // ---- stage biases + c0 into smem ----
    for (int i = tid; i < 1024; i += 256) {
        int g = i >> 8, m = i & 255;
        *reinterpret_cast<float*>(smp + SM_BIAS + i * 4) = g_bias[g][s][m];
    }
    *reinterpret_cast<float*>(smp + SM_C0 + tid * 4) = c0[s * 256 + tid];
    __syncthreads();  // A + bias/c0 visible CTA-wide

    // ---- warp/lane geometry: warp = 16 tokens x (4 gates x 16 m) ----
    const int w    = tid >> 5;
    const int lane = tid & 31;
    const int wr   = w >> 1;  // token row group (0..3): tokens wr*16..wr*16+15
    const int wc   = w & 1;   // m column group (0..1)
    const int lrow  = lane & 15;
    const int lcolb = (lane >> 4) * 16;

    const uint32_t arow = (uint32_t)(wr * 16 + lrow);
    const uint32_t arb = arow * 128, arx = (arow & 7) << 4;
    uint32_t brb[4], brx[4];
#pragma unroll
    for (int g = 0; g < 4; g++) {
        uint32_t brr = (uint32_t)(g * 32 + wc * 16) + (uint32_t)lrow;
        brb[g] = brr * 128;
        brx[g] = (brr & 7) << 4;
    }
    const uint32_t abh = smbase + SM_AH;

    const int qrow = lane >> 2, qcol = lane & 3;
    const float* bias_s = reinterpret_cast<const float*>(smp + SM_BIAS);
    const float* c0_s   = reinterpret_cast<const float*>(smp + SM_C0);

#pragma unroll 1
    for (int mq = 0; mq < 8; mq++) {
        const int p = mq & 1;
        const uint32_t bb = smbase + SM_BB + (uint32_t)p * 16384u;
        const int mbase = mq * 32 + wc * 16;

        // wait B[mq] data ready
        MBAR_WAIT_PARITY(mb_full[p], (uint32_t)((mq >> 1) & 1));

        float acc[4][2][4];  // [gate][n-half][frag]
#pragma unroll
        for (int g = 0; g < 4; g++) {
#pragma unroll
            for (int h = 0; h < 2; h++) {
#pragma unroll
                for (int q = 0; q < 4; q++) {
                    acc[g][h][q] = 0.0f;
                }
            }
        }

        // ---- 1-pass fp16 mainloop ----
#pragma unroll
        for (int k = 0; k < 4; k++) {
            const uint32_t kc = (uint32_t)lcolb + (uint32_t)k * 32;
            uint32_t a0[4];
            ldsm4(a0[0], a0[1], a0[2], a0[3], abh + arb + (kc ^ arx));
#pragma unroll
            for (int gp = 0; gp < 2; gp++) {
                uint32_t bh[2][4];
#pragma unroll
                for (int g2 = 0; g2 < 2; g2++) {
                    int g = gp * 2 + g2;
                    ldsm4(bh[g2][0], bh[g2][1], bh[g2][2], bh[g2][3],
                          bb + brb[g] + (kc ^ brx[g]));
                }
#pragma unroll
                for (int g2 = 0; g2 < 2; g2++) {
                    int g = gp * 2 + g2;
                    mma16816(acc[g][0], a0, bh[g2][0], bh[g2][2]);
                    mma16816(acc[g][1], a0, bh[g2][1], bh[g2][3]);
                }
            }
        }

        // release B buffer p (reads done for this warp)
        MBAR_ARRIVE(mb_rd[p]);

        // prefetch B[mq+1] into the other buffer (overlaps other warps' work)
        if (mq < 7) {
            const int np = 1 - p;
            const int mn = mq + 1;
            if (mq >= 1) {
                MBAR_WAIT_PARITY(mb_rd[np], (uint32_t)((((mq + 1) >> 1) - 1) & 1));
            }
            const uint32_t bufb = smbase + SM_BB + (uint32_t)np * 16384u;
            for (int c = tid; c < 1024; c += 256) {
                int r = c >> 3, ck = c & 7;
                int g = r >> 5, ml = r & 31;
                uint32_t off = swz((uint32_t)r, (uint32_t)ck * 16);
                CP_ASYNC16(bufb + off,
                           __cvta_generic_to_global(&g_wf16[g][s][mn * 32 + ml][ck * 8]));
            }
            CP_ASYNC_MBAR_ARRIVE_NOINC(mb_full[np]);
        }

        // ---- fp32 epilogue (pre-scaled sigmoid args; float2 bias/c0) ----
        float2 bia2[4][2];
        float2 c02[2];
#pragma unroll
        for (int h = 0; h < 2; h++) {
            int m = mbase + h * 8 + qcol * 2;
#pragma unroll
            for (int g = 0; g < 4; g++) {
                bia2[g][h] = *reinterpret_cast<const float2*>(&bias_s[g * 256 + m]);
            }
            c02[h] = *reinterpret_cast<const float2*>(&c0_s[m]);
        }

#pragma unroll
        for (int rp = 0; rp < 2; rp++) {
            int token = n0 + wr * 16 + qrow + rp * 8;
#pragma unroll
            for (int h = 0; h < 2; h++) {
                float hv0, hv1;
#pragma unroll
                for (int cp = 0; cp < 2; cp++) {
                    int idx = rp * 2 + cp;
                    float bI  = (cp == 0) ? bia2[0][h].x : bia2[0][h].y;
                    float bF  = (cp == 0) ? bia2[1][h].x : bia2[1][h].y;
                    float bG2 = (cp == 0) ? bia2[2][h].x : bia2[2][h].y;
                    float bO  = (cp == 0) ? bia2[3][h].x : bia2[3][h].y;
                    float cv  = (cp == 0) ? c02[h].x : c02[h].y;
                    float iv = sigmoid_ps(acc[0][h][idx] + bI);
                    float fv = sigmoid_ps(acc[1][h][idx] + bF);
                    float gv = tanh_f(acc[2][h][idx] + bG2);
                    float ov = sigmoid_ps(acc[3][h][idx] + bO);
                    float cc = fmaf(fv, cv, iv * gv);
                    float hh = ov * tanh_f(cc);
                    if (cp == 0) { hv0 = hh; } else { hv1 = hh; }
                }
                float2 hv;
                hv.x = hv0;
                hv.y = hv1;
                *reinterpret_cast<float2*>(
                    out + (size_t)token * (SS * MM) + s * 256 + mbase + h * 8 + qcol * 2) = hv;
            }
        }
    }
}

// ---------------------------------------------------------------------------
// launch
// ---------------------------------------------------------------------------
extern "C" void kernel_launch(void* const* d_in, const int* in_sizes, int n_in,
                              void* d_out, int out_size) {
    const float* mod = (const float*)d_in[0];
    const float* h0  = (const float*)d_in[1];
    const float* c0  = (const float*)d_in[2];
    const float* Wx  = (const float*)d_in[3];
    const float* bx  = (const float*)d_in[4];
    const float* Wi  = (const float*)d_in[5];
    const float* bi  = (const float*)d_in[6];
    const float* Wf  = (const float*)d_in[7];
    const float* bf  = (const float*)d_in[8];
    const float* Wg  = (const float*)d_in[9];
    const float* bg  = (const float*)d_in[10];
    const float* Wo  = (const float*)d_in[11];
    const float* bo  = (const float*)d_in[12];
    float* out = (float*)d_out;

    cudaFuncSetAttribute(precompute_kernel,
                         cudaFuncAttributeMaxDynamicSharedMemorySize, PC_SZ);
    cudaFuncSetAttribute(lstm_mma_kernel,
                         cudaFuncAttributeMaxDynamicSharedMemorySize, SM_SZ);

    precompute_kernel<<<dim3(SS, 4, 4), 256, PC_SZ>>>(
        Wx, bx, Wi, bi, Wf, bf, Wg, bg, Wo, bo, h0);

    lstm_mma_kernel<<<dim3(NTOK / 64, 1, SS), 256, SM_SZ>>>(mod, c0, out);
}

// round 15
// speedup vs baseline: 1.1338x; 1.1338x over previous
#include <cuda_runtime.h>
#include <cuda_bf16.h>
#include <cuda_fp16.h>
#include <cstdint>

// Problem constants
#define SS 8        // streams
#define II 64       // modulations per stream
#define MM 256      // features per stream
#define NTOK 16384  // batch

// Fused weights (fp16): W~_g[s] = Wg[:, :, 0:M] @ Wx[s]  -> [4][S][M][64]
__device__ __half g_wf16[4][SS][MM][II];
// Fused biases:  b~_g[s,m] = bg + Wg_x@bx + Wg_h@h0
__device__ float g_bias[4][SS][MM];

// ---------------------------------------------------------------------------
// helpers
// ---------------------------------------------------------------------------
// hardware tanh (MUFU.TANH, sm_75+): 1 MUFU op, rel err ~2^-11
__device__ __forceinline__ float tanh_f(float x) {
    float y;
    asm("tanh.approx.f32 %0, %1;" : "=f"(y) : "f"(x));
    return y;
}
// sigmoid via hw tanh: sigma(x) = 0.5 + 0.5*tanh(x/2)  (1 MUFU + 2 FMA)
__device__ __forceinline__ float sigmoid_f(float x) {
    float y;
    asm("tanh.approx.f32 %0, %1;" : "=f"(y) : "f"(0.5f * x));
    return fmaf(0.5f, y, 0.5f);
}

// pack two fp32 into fp16x2 (a in low half, b in high half), as u32
__device__ __forceinline__ uint32_t pack_h2_u32(float a, float b) {
    uint32_t r;
    asm("cvt.rn.f16x2.f32 %0, %1, %2;" : "=r"(r) : "f"(b), "f"(a));
    return r;
}

__device__ __forceinline__ uint32_t smem_u32(const void* p) {
    uint32_t a;
    asm("{ .reg .u64 t; cvta.to.shared.u64 t, %1; cvt.u32.u64 %0, t; }"
        : "=r"(a) : "l"(p));
    return a;
}

__device__ __forceinline__ void ldsm4(uint32_t& r0, uint32_t& r1,
                                      uint32_t& r2, uint32_t& r3, uint32_t addr) {
    asm volatile("ldmatrix.sync.aligned.m8n8.x4.shared.b16 {%0,%1,%2,%3}, [%4];"
                 : "=r"(r0), "=r"(r1), "=r"(r2), "=r"(r3) : "r"(addr));
}
__device__ __forceinline__ void ldsm4t(uint32_t& r0, uint32_t& r1,
                                       uint32_t& r2, uint32_t& r3, uint32_t addr) {
    asm volatile("ldmatrix.sync.aligned.m8n8.x4.trans.shared.b16 {%0,%1,%2,%3}, [%4];"
                 : "=r"(r0), "=r"(r1), "=r"(r2), "=r"(r3) : "r"(addr));
}

__device__ __forceinline__ void mma16816(float* c, const uint32_t* a,
                                         uint32_t b0, uint32_t b1) {
    asm volatile(
        "mma.sync.aligned.m16n8k16.row.col.f32.f16.f16.f32 "
        "{%0,%1,%2,%3}, {%4,%5,%6,%7}, {%8,%9}, {%0,%1,%2,%3};"
        : "+f"(c[0]), "+f"(c[1]), "+f"(c[2]), "+f"(c[3])
        : "r"(a[0]), "r"(a[1]), "r"(a[2]), "r"(a[3]), "r"(b0), "r"(b1));
}

// swizzled smem byte offset for rows of 128B: XOR 16B-chunk by (row&7)
__device__ __forceinline__ uint32_t swz(uint32_t row, uint32_t colbyte) {
    return row * 128u + (colbyte ^ ((row & 7u) << 4));
}

// convert 8 consecutive fp32 at src to 4 packed fp16x2 words
__device__ __forceinline__ uint4 cvt8_f32_to_h2(const float* src) {
    float4 v0 = *reinterpret_cast<const float4*>(src);
    float4 v1 = *reinterpret_cast<const float4*>(src + 4);
    uint4 r;
    r.x = pack_h2_u32(v0.x, v0.y);
    r.y = pack_h2_u32(v0.z, v0.w);
    r.z = pack_h2_u32(v1.x, v1.y);
    r.w = pack_h2_u32(v1.z, v1.w);
    return r;
}

#define CP_ASYNC16(dst, gsrc) \
    asm volatile("cp.async.cg.shared.global [%0], [%1], 16;" \
                 :: "r"(dst), "l"(gsrc) : "memory")

#define MBAR_INIT(addr, cnt) \
    asm volatile("mbarrier.init.shared.b64 [%0], %1;" :: "r"(addr), "r"(cnt) : "memory")
#define MBAR_ARRIVE(addr) \
    asm volatile("mbarrier.arrive.shared.b64 _, [%0];" :: "r"(addr) : "memory")
#define CP_ASYNC_MBAR_ARRIVE_NOINC(addr) \
    asm volatile("cp.async.mbarrier.arrive.noinc.shared::cta.b64 [%0];" :: "r"(addr) : "memory")

#define MBAR_WAIT_PARITY(addr, par) do {                                        \
    uint32_t _mb = (addr);                                                      \
    uint32_t _pa = (par);                                                       \
    uint32_t _done;                                                             \
    asm volatile(                                                               \
        "{\n\t"                                                                 \
        ".reg .pred p;\n\t"                                                     \
        "mbarrier.try_wait.parity.acquire.cta.shared::cta.b64 p, [%1], %2;\n\t" \
        "selp.b32 %0, 1, 0, p;\n\t"                                             \
        "}" : "=r"(_done) : "r"(_mb), "r"(_pa) : "memory");                     \
    if (!_done) {                                                               \
        asm volatile(                                                           \
            "{\n\t"                                                             \
            ".reg .pred P1;\n\t"                                                \
            "WL_%=:\n\t"                                                        \
            "mbarrier.try_wait.parity.acquire.cta.shared::cta.b64 P1, [%0], %1, 0x989680;\n\t" \
            "@P1 bra.uni WD_%=;\n\t"                                            \
            "bra.uni WL_%=;\n\t"                                                \
            "WD_%=:\n\t"                                                        \
            "}" :: "r"(_mb), "r"(_pa) : "memory");                              \
    }                                                                           \
} while (0)

// ---------------------------------------------------------------------------
// Kernel 1: weight/bias fusion via tensor cores
// grid = (S, 4 gates, 4 m-blocks of 64), block = 256 (8 warps), 2 CTAs/SM
// Bias x-part computed from the fp16-staged A in smem (no global re-read);
// h-part guarded by an h0-nonzero check (h0 == 0 in this problem's inputs).
// ---------------------------------------------------------------------------
#define PC_A   0u
#define PC_B   32768u
#define PC_RED 65536u     // 256 floats
#define PC_BX  66560u     // 256 floats
#define PC_H0  67584u     // 256 floats
#define PC_SZ  68608u

__global__ __launch_bounds__(256, 2)
void precompute_kernel(const float* __restrict__ Wx, const float* __restrict__ bx,
                       const float* __restrict__ Wi, const float* __restrict__ bi,
                       const float* __restrict__ Wf, const float* __restrict__ bf,
                       const float* __restrict__ Wg, const float* __restrict__ bg,
                       const float* __restrict__ Wo, const float* __restrict__ bo,
                       const float* __restrict__ h0) {
    extern __shared__ char psm[];
    const uint32_t smb = smem_u32(psm);

    const int s    = blockIdx.x;
    const int gate = blockIdx.y;
    const int m0   = blockIdx.z * 64;
    const int tid  = threadIdx.x;

    const float* WG;
    const float* bG;
    switch (gate) {
        case 0:  WG = Wi; bG = bi; break;
        case 1:  WG = Wf; bG = bf; break;
        case 2:  WG = Wg; bG = bg; break;
        default: WG = Wo; bG = bo; break;
    }

    // ---- stage bx + h0 (1KB each) ----
    reinterpret_cast<float*>(psm + PC_BX)[tid] = bx[s * 256 + tid];
    reinterpret_cast<float*>(psm + PC_H0)[tid] = h0[s * 256 + tid];

    // ---- stage A: Wg x-half rows m0..m0+63, fp32 -> fp16, 512B rows ----
    for (int idx = tid; idx < 2048; idx += 256) {  // 64 rows x 32 chunks
        int mm = idx >> 5, ck = idx & 31;
        const float* src = WG + (size_t)(s * 256 + m0 + mm) * 512 + ck * 8;
        uint4 v = cvt8_f32_to_h2(src);
        uint32_t off = (uint32_t)mm * 512u + (((uint32_t)ck * 16u) ^ (((uint32_t)mm & 7u) << 4));
        *reinterpret_cast<uint4*>(psm + PC_A + off) = v;
    }
    // ---- stage B: Wx[s] [k=256][i=64], fp32 -> fp16, SW128 rows ----
    for (int idx = tid; idx < 2048; idx += 256) {  // 256 rows x 8 chunks
        int k = idx >> 3, ck = idx & 7;
        const float* src = Wx + (size_t)s * 16384 + k * 64 + ck * 8;
        uint4 v = cvt8_f32_to_h2(src);
        *reinterpret_cast<uint4*>(psm + PC_B + swz((uint32_t)k, (uint32_t)ck * 16)) = v;
    }
    __syncthreads();

    // ---- mma: warp tile = 16 m x 32 i, K = 256 in 16 steps ----
    const int w    = tid >> 5;
    const int lane = tid & 31;
    const int wm   = w >> 1;   // m group (0..3)
    const int wi   = w & 1;    // i group (0..1): i base = wi*32
    const int lrow  = lane & 15;
    const int lhalf = lane >> 4;

    const uint32_t arow = (uint32_t)(wm * 16 + lrow);
    const uint32_t abase = smb + PC_A + arow * 512u;
    const uint32_t axor  = (arow & 7u) << 4;

    // trans-ldsm lane addressing for B ([k][i] storage -> [i][k] fragment)
    const uint32_t krow_off = (uint32_t)((lane & 7) + ((lane & 16) >> 1));  // +8 for lanes>=16
    const uint32_t ib_off   = (uint32_t)((lane & 8) << 1);                  // +16B for lanes&8

    float acc[4][4];
#pragma unroll
    for (int ng = 0; ng < 4; ng++) {
#pragma unroll
        for (int q = 0; q < 4; q++) {
            acc[ng][q] = 0.0f;
        }
    }

#pragma unroll
    for (int ks = 0; ks < 16; ks++) {
        uint32_t a[4];
        ldsm4(a[0], a[1], a[2], a[3],
              abase + ((((uint32_t)(ks * 2 + lhalf)) * 16u) ^ axor));
        uint32_t krow = (uint32_t)(ks * 16) + krow_off;
        uint32_t brow = smb + PC_B + krow * 128u;
        uint32_t bxor = (krow & 7u) << 4;
        uint32_t b0[4], b1[4];
        ldsm4t(b0[0], b0[1], b0[2], b0[3],
               brow + (((uint32_t)(wi * 64 + 0) + ib_off) ^ bxor));
        ldsm4t(b1[0], b1[1], b1[2], b1[3],
               brow + (((uint32_t)(wi * 64 + 32) + ib_off) ^ bxor));
        mma16816(acc[0], a, b0[0], b0[2]);  // i 0-7
        mma16816(acc[1], a, b0[1], b0[3]);  // i 8-15
        mma16816(acc[2], a, b1[0], b1[2]);  // i 16-23
        mma16816(acc[3], a, b1[1], b1[3]);  // i 24-31
    }

    // ---- store fused fp16 weights ----
    {
        const int qrow = lane >> 2, qcol = lane & 3;
        const int mrow = m0 + wm * 16 + qrow;
#pragma unroll
        for (int ng = 0; ng < 4; ng++) {
            int icol = wi * 32 + ng * 8 + qcol * 2;
            *reinterpret_cast<uint32_t*>(&g_wf16[gate][s][mrow][icol]) =
                pack_h2_u32(acc[ng][0], acc[ng][1]);
            *reinterpret_cast<uint32_t*>(&g_wf16[gate][s][mrow + 8][icol]) =
                pack_h2_u32(acc[ng][2], acc[ng][3]);
        }
    }

    // ---- fused bias: x-part from fp16-staged A in smem; h-part guarded ----
    {
        float* red = reinterpret_cast<float*>(psm + PC_RED);
        const float* bx_s = reinterpret_cast<const float*>(psm + PC_BX);
        const float* h0_s = reinterpret_cast<const float*>(psm + PC_H0);
        const int mm = tid & 63, part = tid >> 6;
        float p = 0.0f;
        if (part < 2) {
            // k range [part*128, part*128+128) from staged fp16 A
            const uint32_t rowbase = (uint32_t)mm * 512u;
            const uint32_t rxor = ((uint32_t)mm & 7u) << 4;
#pragma unroll 4
            for (int j = 0; j < 16; j++) {
                uint32_t ck = (uint32_t)(part * 16 + j);
                uint4 v = *reinterpret_cast<const uint4*>(
                    psm + PC_A + rowbase + ((ck * 16u) ^ rxor));
                const float* bp = bx_s + part * 128 + j * 8;
                float2 f0 = __half22float2(*reinterpret_cast<const __half2*>(&v.x));
                float2 f1 = __half22float2(*reinterpret_cast<const __half2*>(&v.y));
                float2 f2 = __half22float2(*reinterpret_cast<const __half2*>(&v.z));
                float2 f3 = __half22float2(*reinterpret_cast<const __half2*>(&v.w));
                p = fmaf(f0.x, bp[0], p); p = fmaf(f0.y, bp[1], p);
                p = fmaf(f1.x, bp[2], p); p = fmaf(f1.y, bp[3], p);
                p = fmaf(f2.x, bp[4], p); p = fmaf(f2.y, bp[5], p);
                p = fmaf(f3.x, bp[6], p); p = fmaf(f3.y, bp[7], p);
            }
        } else {
            const int seg = part - 2;
            const float4* hseg = reinterpret_cast<const float4*>(h0_s + seg * 128);
            float any = 0.0f;
#pragma unroll 4
            for (int k = 0; k < 32; k++) {
                float4 hv = hseg[k];
                any += fabsf(hv.x) + fabsf(hv.y) + fabsf(hv.z) + fabsf(hv.w);
            }
            if (any != 0.0f) {
                const float4* a = reinterpret_cast<const float4*>(
                    WG + (size_t)(s * 256 + m0 + mm) * 512 + 256 + seg * 128);
#pragma unroll 4
                for (int k = 0; k < 32; k++) {
                    float4 av = a[k], hv = hseg[k];
                    p += av.x * hv.x + av.y * hv.y + av.z * hv.z + av.w * hv.w;
                }
            }
        }
        red[part * 64 + mm] = p;
        __syncthreads();
        if (tid < 64) {
            g_bias[gate][s][m0 + tid] = bG[s * 256 + m0 + tid] +
                red[tid] + red[64 + tid] + red[128 + tid] + red[192 + tid];
        }
    }
}

// ---------------------------------------------------------------------------
// Kernel 2: main LSTM step (R12 config, validated: mma.sync fp16 1-pass GEMM;
// persistent over m-octants, mbarrier-pipelined B buffers; fp32 epilogue)
// grid = (token-tiles=128, 1, stream=8) = 1024 CTAs, block = 256 (8 warps)
// ---------------------------------------------------------------------------
#define SM_AH   0u
#define SM_BB   16384u     // buffer p at SM_BB + p*16384
#define SM_BIAS 49152u     // 1024 floats
#define SM_C0   53248u     // 256 floats
#define SM_MB   54272u     // full0, full1, rd0, rd1 (8B each)
#define SM_SZ   54304u

__global__ __launch_bounds__(256, 2)
void lstm_mma_kernel(const float* __restrict__ mod,
                     const float* __restrict__ c0,
                     float* __restrict__ out) {
    extern __shared__ char sm[];
    char* smp = sm;
    const uint32_t smbase = smem_u32(sm);

    const int s   = blockIdx.z;
    const int n0  = blockIdx.x * 128; // token base
    const int tid = threadIdx.x;

    const uint32_t mb_full[2] = {smbase + SM_MB, smbase + SM_MB + 8};
    const uint32_t mb_rd[2]   = {smbase + SM_MB + 16, smbase + SM_MB + 24};

    if (tid == 0) {
        MBAR_INIT(mb_full[0], 256);
        MBAR_INIT(mb_full[1], 256);
        MBAR_INIT(mb_rd[0], 256);
        MBAR_INIT(mb_rd[1], 256);
    }
    __syncthreads();

    // ---- kick off B[0] via cp.async into buffer 0, tracked by full[0] ----
    for (int c = tid; c < 1024; c += 256) {
        int r = c >> 3, ck = c & 7;
        int g = r >> 5, ml = r & 31;
        uint32_t off = swz((uint32_t)r, (uint32_t)ck * 16);
        CP_ASYNC16(smbase + SM_BB + off,
                   __cvta_generic_to_global(&g_wf16[g][s][ml][ck * 8]));
    }
    CP_ASYNC_MBAR_ARRIVE_NOINC(mb_full[0]);

    // ---- stage A (tokens): fp32 -> fp16, SW128 (overlaps B0 copy) ----
    for (int c = tid; c < 1024; c += 256) {
        int row = c >> 3, ck = c & 7;  // 16B chunk = 8 fp16
        const float* src = mod + (size_t)(n0 + row) * (SS * II) + s * II + ck * 8;
        uint4 v = cvt8_f32_to_h2(src);
        uint32_t off = swz((uint32_t)row, (uint32_t)ck * 16);
        *reinterpret_cast<uint4*>(smp + SM_AH + off) = v;
    }

    // ---- stage biases + c0 into smem ----
    for (int i = tid; i < 1024; i += 256) {
        int g = i >> 8, m = i & 255;
        *reinterpret_cast<float*>(smp + SM_BIAS + i * 4) = g_bias[g][s][m];
    }
    *reinterpret_cast<float*>(smp + SM_C0 + tid * 4) = c0[s * 256 + tid];
    __syncthreads();  // A + bias/c0 visible CTA-wide

    // ---- warp/lane geometry ----
    const int w    = tid >> 5;
    const int lane = tid & 31;
    const int wr   = w >> 1;  // token row group (0..3)
    const int wc   = w & 1;   // m column group (0..1)
    const int lrow  = lane & 15;
    const int lcolb = (lane >> 4) * 16;

    const uint32_t arow0 = (uint32_t)(wr * 32 + lrow);
    const uint32_t arow1 = (uint32_t)(wr * 32 + 16 + lrow);
    const uint32_t arb0 = arow0 * 128, arx0 = (arow0 & 7) << 4;
    const uint32_t arb1 = arow1 * 128, arx1 = (arow1 & 7) << 4;
    uint32_t brb[4], brx[4];
#pragma unroll
    for (int g = 0; g < 4; g++) {
        uint32_t brr = (uint32_t)(g * 32 + wc * 16) + (uint32_t)lrow;
        brb[g] = brr * 128;
        brx[g] = (brr & 7) << 4;
    }
    const uint32_t abh = smbase + SM_AH;

    const int qrow = lane >> 2, qcol = lane & 3;
    const float* bias_s = reinterpret_cast<const float*>(smp + SM_BIAS);
    const float* c0_s   = reinterpret_cast<const float*>(smp + SM_C0);

#pragma unroll 1
    for (int mq = 0; mq < 8; mq++) {
        const int p = mq & 1;
        const uint32_t bb = smbase + SM_BB + (uint32_t)p * 16384u;

        // wait B[mq] data ready
        MBAR_WAIT_PARITY(mb_full[p], (uint32_t)((mq >> 1) & 1));

        float acc[2][4][2][4];  // [token-tile][gate][n-half][frag]
#pragma unroll
        for (int mt = 0; mt < 2; mt++) {
#pragma unroll
            for (int g = 0; g < 4; g++) {
#pragma unroll
                for (int h = 0; h < 2; h++) {
#pragma unroll
                    for (int q = 0; q < 4; q++) {
                        acc[mt][g][h][q] = 0.0f;
                    }
                }
            }
        }

        // ---- 1-pass fp16 mainloop ----
#pragma unroll
        for (int k = 0; k < 4; k++) {
            const uint32_t kc = (uint32_t)lcolb + (uint32_t)k * 32;
            uint32_t a0[4], a1[4];
            ldsm4(a0[0], a0[1], a0[2], a0[3], abh + arb0 + (kc ^ arx0));
            ldsm4(a1[0], a1[1], a1[2], a1[3], abh + arb1 + (kc ^ arx1));
#pragma unroll
            for (int gp = 0; gp < 2; gp++) {
                uint32_t bh[2][4];
#pragma unroll
                for (int g2 = 0; g2 < 2; g2++) {
                    int g = gp * 2 + g2;
                    ldsm4(bh[g2][0], bh[g2][1], bh[g2][2], bh[g2][3],
                          bb + brb[g] + (kc ^ brx[g]));
                }
#pragma unroll
                for (int g2 = 0; g2 < 2; g2++) {
                    int g = gp * 2 + g2;
                    mma16816(acc[0][g][0], a0, bh[g2][0], bh[g2][2]);
                    mma16816(acc[0][g][1], a0, bh[g2][1], bh[g2][3]);
                    mma16816(acc[1][g][0], a1, bh[g2][0], bh[g2][2]);
                    mma16816(acc[1][g][1], a1, bh[g2][1], bh[g2][3]);
                }
            }
        }

        // release B buffer p (reads done for this warp)
        MBAR_ARRIVE(mb_rd[p]);

        // prefetch B[mq+1] into the other buffer (overlaps other warps' work)
        if (mq < 7) {
            const int np = 1 - p;
            const int mn = mq + 1;
            if (mq >= 1) {
                // wait until all warps finished reading buffer np at iteration mq-1
                MBAR_WAIT_PARITY(mb_rd[np], (uint32_t)((((mq + 1) >> 1) - 1) & 1));
            }
            const uint32_t bufb = smbase + SM_BB + (uint32_t)np * 16384u;
            for (int c = tid; c < 1024; c += 256) {
                int r = c >> 3, ck = c & 7;
                int g = r >> 5, ml = r & 31;
                uint32_t off = swz((uint32_t)r, (uint32_t)ck * 16);
                CP_ASYNC16(bufb + off,
                           __cvta_generic_to_global(&g_wf16[g][s][mn * 32 + ml][ck * 8]));
            }
            CP_ASYNC_MBAR_ARRIVE_NOINC(mb_full[np]);
        }

        // ---- fp32 epilogue (all 4 gates live in this thread's registers) ----
        const int mbase = mq * 32 + wc * 16;

        float bia[4][2][2];  // [gate][n-half][cp]
        float c0v[2][2];
#pragma unroll
        for (int h = 0; h < 2; h++) {
#pragma unroll
            for (int cp = 0; cp < 2; cp++) {
                int m = mbase + h * 8 + qcol * 2 + cp;
#pragma unroll
                for (int g = 0; g < 4; g++) {
                    bia[g][h][cp] = bias_s[g * 256 + m];
                }
                c0v[h][cp] = c0_s[m];
            }
        }

#pragma unroll
        for (int mt = 0; mt < 2; mt++) {
#pragma unroll
            for (int rp = 0; rp < 2; rp++) {
                int token = n0 + wr * 32 + mt * 16 + qrow + rp * 8;
#pragma unroll
                for (int h = 0; h < 2; h++) {
                    float hv0, hv1;
#pragma unroll
                    for (int cp = 0; cp < 2; cp++) {
                        int idx = rp * 2 + cp;
                        float iv = sigmoid_f(acc[mt][0][h][idx] + bia[0][h][cp]);
                        float fv = sigmoid_f(acc[mt][1][h][idx] + bia[1][h][cp]);
                        float gv = tanh_f(acc[mt][2][h][idx] + bia[2][h][cp]);
                        float ov = sigmoid_f(acc[mt][3][h][idx] + bia[3][h][cp]);
                        float cc = fmaf(fv, c0v[h][cp], iv * gv);
                        float hh = ov * tanh_f(cc);
                        if (cp == 0) { hv0 = hh; } else { hv1 = hh; }
                    }
                    float2 hv;
                    hv.x = hv0;
                    hv.y = hv1;
                    *reinterpret_cast<float2*>(
                        out + (size_t)token * (SS * MM) + s * 256 + mbase + h * 8 + qcol * 2) = hv;
                }
            }
        }
    }
}

// ---------------------------------------------------------------------------
// launch
// ---------------------------------------------------------------------------
extern "C" void kernel_launch(void* const* d_in, const int* in_sizes, int n_in,
                              void* d_out, int out_size) {
    const float* mod = (const float*)d_in[0];
    const float* h0  = (const float*)d_in[1];
    const float* c0  = (const float*)d_in[2];
    const float* Wx  = (const float*)d_in[3];
    const float* bx  = (const float*)d_in[4];
    const float* Wi  = (const float*)d_in[5];
    const float* bi  = (const float*)d_in[6];
    const float* Wf  = (const float*)d_in[7];
    const float* bf  = (const float*)d_in[8];
    const float* Wg  = (const float*)d_in[9];
    const float* bg  = (const float*)d_in[10];
    const float* Wo  = (const float*)d_in[11];
    const float* bo  = (const float*)d_in[12];
    float* out = (float*)d_out;

    cudaFuncSetAttribute(precompute_kernel,
                         cudaFuncAttributeMaxDynamicSharedMemorySize, PC_SZ);
    cudaFuncSetAttribute(lstm_mma_kernel,
                         cudaFuncAttributeMaxDynamicSharedMemorySize, SM_SZ);

    precompute_kernel<<<dim3(SS, 4, 4), 256, PC_SZ>>>(
        Wx, bx, Wi, bi, Wf, bf, Wg, bg, Wo, bo, h0);

    lstm_mma_kernel<<<dim3(NTOK / 128, 1, SS), 256, SM_SZ>>>(mod, c0, out);
}

// round 16
// speedup vs baseline: 1.1753x; 1.0366x over previous
#include <cuda_runtime.h>
#include <cuda_bf16.h>
#include <cuda_fp16.h>
#include <cstdint>

// Problem constants
#define SS 8        // streams
#define II 64       // modulations per stream
#define MM 256      // features per stream
#define NTOK 16384  // batch

// Fused weights (fp16): W~_g[s] = Wg[:, :, 0:M] @ Wx[s]  -> [4][S][M][64]
__device__ __half g_wf16[4][SS][MM][II];
// Fused biases:  b~_g[s,m] = bg + Wg_x@bx + Wg_h@h0
__device__ float g_bias[4][SS][MM];

// ---------------------------------------------------------------------------
// helpers
// ---------------------------------------------------------------------------
// hardware tanh (MUFU.TANH, sm_75+): 1 MUFU op, rel err ~2^-11
__device__ __forceinline__ float tanh_f(float x) {
    float y;
    asm("tanh.approx.f32 %0, %1;" : "=f"(y) : "f"(x));
    return y;
}
// sigmoid via hw tanh: sigma(x) = 0.5 + 0.5*tanh(x/2)  (1 MUFU + 2 FMA)
__device__ __forceinline__ float sigmoid_f(float x) {
    float y;
    asm("tanh.approx.f32 %0, %1;" : "=f"(y) : "f"(0.5f * x));
    return fmaf(0.5f, y, 0.5f);
}

// pack two fp32 into fp16x2 (a in low half, b in high half), as u32
__device__ __forceinline__ uint32_t pack_h2_u32(float a, float b) {
    uint32_t r;
    asm("cvt.rn.f16x2.f32 %0, %1, %2;" : "=r"(r) : "f"(b), "f"(a));
    return r;
}

__device__ __forceinline__ uint32_t smem_u32(const void* p) {
    uint32_t a;
    asm("{ .reg .u64 t; cvta.to.shared.u64 t, %1; cvt.u32.u64 %0, t; }"
        : "=r"(a) : "l"(p));
    return a;
}

__device__ __forceinline__ void ldsm4(uint32_t& r0, uint32_t& r1,
                                      uint32_t& r2, uint32_t& r3, uint32_t addr) {
    asm volatile("ldmatrix.sync.aligned.m8n8.x4.shared.b16 {%0,%1,%2,%3}, [%4];"
                 : "=r"(r0), "=r"(r1), "=r"(r2), "=r"(r3) : "r"(addr));
}
__device__ __forceinline__ void ldsm4t(uint32_t& r0, uint32_t& r1,
                                       uint32_t& r2, uint32_t& r3, uint32_t addr) {
    asm volatile("ldmatrix.sync.aligned.m8n8.x4.trans.shared.b16 {%0,%1,%2,%3}, [%4];"
                 : "=r"(r0), "=r"(r1), "=r"(r2), "=r"(r3) : "r"(addr));
}

__device__ __forceinline__ void mma16816(float* c, const uint32_t* a,
                                         uint32_t b0, uint32_t b1) {
    asm volatile(
        "mma.sync.aligned.m16n8k16.row.col.f32.f16.f16.f32 "
        "{%0,%1,%2,%3}, {%4,%5,%6,%7}, {%8,%9}, {%0,%1,%2,%3};"
        : "+f"(c[0]), "+f"(c[1]), "+f"(c[2]), "+f"(c[3])
        : "r"(a[0]), "r"(a[1]), "r"(a[2]), "r"(a[3]), "r"(b0), "r"(b1));
}

// swizzled smem byte offset for rows of 128B: XOR 16B-chunk by (row&7)
__device__ __forceinline__ uint32_t swz(uint32_t row, uint32_t colbyte) {
    return row * 128u + (colbyte ^ ((row & 7u) << 4));
}

// convert 8 consecutive fp32 at src to 4 packed fp16x2 words
__device__ __forceinline__ uint4 cvt8_f32_to_h2(const float* src) {
    float4 v0 = *reinterpret_cast<const float4*>(src);
    float4 v1 = *reinterpret_cast<const float4*>(src + 4);
    uint4 r;
    r.x = pack_h2_u32(v0.x, v0.y);
    r.y = pack_h2_u32(v0.z, v0.w);
    r.z = pack_h2_u32(v1.x, v1.y);
    r.w = pack_h2_u32(v1.z, v1.w);
    return r;
}

#define CP_ASYNC16(dst, gsrc) \
    asm volatile("cp.async.cg.shared.global [%0], [%1], 16;" \
                 :: "r"(dst), "l"(gsrc) : "memory")

#define MBAR_INIT(addr, cnt) \
    asm volatile("mbarrier.init.shared.b64 [%0], %1;" :: "r"(addr), "r"(cnt) : "memory")
#define MBAR_ARRIVE(addr) \
    asm volatile("mbarrier.arrive.shared.b64 _, [%0];" :: "r"(addr) : "memory")
#define CP_ASYNC_MBAR_ARRIVE_NOINC(addr) \
    asm volatile("cp.async.mbarrier.arrive.noinc.shared::cta.b64 [%0];" :: "r"(addr) : "memory")

#define MBAR_WAIT_PARITY(addr, par) do {                                        \
    uint32_t _mb = (addr);                                                      \
    uint32_t _pa = (par);                                                       \
    uint32_t _done;                                                             \
    asm volatile(                                                               \
        "{\n\t"                                                                 \
        ".reg .pred p;\n\t"                                                     \
        "mbarrier.try_wait.parity.acquire.cta.shared::cta.b64 p, [%1], %2;\n\t" \
        "selp.b32 %0, 1, 0, p;\n\t"                                             \
        "}" : "=r"(_done) : "r"(_mb), "r"(_pa) : "memory");                     \
    if (!_done) {                                                               \
        asm volatile(                                                           \
            "{\n\t"                                                             \
            ".reg .pred P1;\n\t"                                                \
            "WL_%=:\n\t"                                                        \
            "mbarrier.try_wait.parity.acquire.cta.shared::cta.b64 P1, [%0], %1, 0x989680;\n\t" \
            "@P1 bra.uni WD_%=;\n\t"                                            \
            "bra.uni WL_%=;\n\t"                                                \
            "WD_%=:\n\t"                                                        \
            "}" :: "r"(_mb), "r"(_pa) : "memory");                              \
    }                                                                           \
} while (0)

// ---------------------------------------------------------------------------
// Kernel 1: weight/bias fusion via tensor cores, 512 threads (16 warps)
// grid = (S, 4 gates, 4 m-blocks of 64), block = 512
// Warp tile = 16m x 16i (wm = w>>2, wi = w&3). Staging loops: 4 iters each.
// Bias x-part from fp16-staged A (smem); h-part guarded by h0-nonzero check.
// ---------------------------------------------------------------------------
#define PC_A   0u
#define PC_B   32768u
#define PC_RED 65536u     // 512 floats
#define PC_BX  67584u     // 256 floats
#define PC_H0  68608u     // 256 floats
#define PC_SZ  69632u

__global__ __launch_bounds__(512, 2)
void precompute_kernel(const float* __restrict__ Wx, const float* __restrict__ bx,
                       const float* __restrict__ Wi, const float* __restrict__ bi,
                       const float* __restrict__ Wf, const float* __restrict__ bf,
                       const float* __restrict__ Wg, const float* __restrict__ bg,
                       const float* __restrict__ Wo, const float* __restrict__ bo,
                       const float* __restrict__ h0) {
    extern __shared__ char psm[];
    const uint32_t smb = smem_u32(psm);

    const int s    = blockIdx.x;
    const int gate = blockIdx.y;
    const int m0   = blockIdx.z * 64;
    const int tid  = threadIdx.x;

    const float* WG;
    const float* bG;
    switch (gate) {
        case 0:  WG = Wi; bG = bi; break;
        case 1:  WG = Wf; bG = bf; break;
        case 2:  WG = Wg; bG = bg; break;
        default: WG = Wo; bG = bo; break;
    }

    // ---- stage bx + h0 (1KB each) ----
    if (tid < 256) {
        reinterpret_cast<float*>(psm + PC_BX)[tid] = bx[s * 256 + tid];
        reinterpret_cast<float*>(psm + PC_H0)[tid] = h0[s * 256 + tid];
    }

    // ---- stage A: Wg x-half rows m0..m0+63, fp32 -> fp16, 512B rows ----
    for (int idx = tid; idx < 2048; idx += 512) {  // 64 rows x 32 chunks
        int mm = idx >> 5, ck = idx & 31;
        const float* src = WG + (size_t)(s * 256 + m0 + mm) * 512 + ck * 8;
        uint4 v = cvt8_f32_to_h2(src);
        uint32_t off = (uint32_t)mm * 512u + (((uint32_t)ck * 16u) ^ (((uint32_t)mm & 7u) << 4));
        *reinterpret_cast<uint4*>(psm + PC_A + off) = v;
    }
    // ---- stage B: Wx[s] [k=256][i=64], fp32 -> fp16, SW128 rows ----
    for (int idx = tid; idx < 2048; idx += 512) {  // 256 rows x 8 chunks
        int k = idx >> 3, ck = idx & 7;
        const float* src = Wx + (size_t)s * 16384 + k * 64 + ck * 8;
        uint4 v = cvt8_f32_to_h2(src);
        *reinterpret_cast<uint4*>(psm + PC_B + swz((uint32_t)k, (uint32_t)ck * 16)) = v;
    }
    __syncthreads();

    // ---- mma: 16 warps, warp tile = 16 m x 16 i, K = 256 in 16 steps ----
    const int w    = tid >> 5;
    const int lane = tid & 31;
    const int wm   = w >> 2;   // m group (0..3)
    const int wi   = w & 3;    // i group (0..3): i base = wi*16
    const int lrow  = lane & 15;
    const int lhalf = lane >> 4;

    const uint32_t arow = (uint32_t)(wm * 16 + lrow);
    const uint32_t abase = smb + PC_A + arow * 512u;
    const uint32_t axor  = (arow & 7u) << 4;

    // trans-ldsm lane addressing for B ([k][i] storage -> [i][k] fragment)
    const uint32_t krow_off = (uint32_t)((lane & 7) + ((lane & 16) >> 1));  // +8 for lanes>=16
    const uint32_t ib_off   = (uint32_t)((lane & 8) << 1);                  // +16B for lanes&8

    float acc[2][4];
#pragma unroll
    for (int ng = 0; ng < 2; ng++) {
#pragma unroll
        for (int q = 0; q < 4; q++) {
            acc[ng][q] = 0.0f;
        }
    }

#pragma unroll
    for (int ks = 0; ks < 16; ks++) {
        uint32_t a[4];
        ldsm4(a[0], a[1], a[2], a[3],
              abase + ((((uint32_t)(ks * 2 + lhalf)) * 16u) ^ axor));
        uint32_t krow = (uint32_t)(ks * 16) + krow_off;
        uint32_t brow = smb + PC_B + krow * 128u;
        uint32_t bxor = (krow & 7u) << 4;
        uint32_t b0[4];
        ldsm4t(b0[0], b0[1], b0[2], b0[3],
               brow + (((uint32_t)(wi * 32) + ib_off) ^ bxor));
        mma16816(acc[0], a, b0[0], b0[2]);  // i 0-7 of warp's 16
        mma16816(acc[1], a, b0[1], b0[3]);  // i 8-15
    }

    // ---- store fused fp16 weights ----
    {
        const int qrow = lane >> 2, qcol = lane & 3;
        const int mrow = m0 + wm * 16 + qrow;
#pragma unroll
        for (int ng = 0; ng < 2; ng++) {
            int icol = wi * 16 + ng * 8 + qcol * 2;
            *reinterpret_cast<uint32_t*>(&g_wf16[gate][s][mrow][icol]) =
                pack_h2_u32(acc[ng][0], acc[ng][1]);
            *reinterpret_cast<uint32_t*>(&g_wf16[gate][s][mrow + 8][icol]) =
                pack_h2_u32(acc[ng][2], acc[ng][3]);
        }
    }

    // ---- fused bias: 8 partials of 64 k per output row ----
    {
        float* red = reinterpret_cast<float*>(psm + PC_RED);
        const float* bx_s = reinterpret_cast<const float*>(psm + PC_BX);
        const float* h0_s = reinterpret_cast<const float*>(psm + PC_H0);
        const int mm = tid & 63, part = tid >> 6;  // part 0..7
        float p = 0.0f;
        if (part < 4) {
            // x-part: k range [part*64, part*64+64) from staged fp16 A
            const uint32_t rowbase = (uint32_t)mm * 512u;
            const uint32_t rxor = ((uint32_t)mm & 7u) << 4;
#pragma unroll
            for (int j = 0; j < 8; j++) {
                uint32_t ck = (uint32_t)(part * 8 + j);
                uint4 v = *reinterpret_cast<const uint4*>(
                    psm + PC_A + rowbase + ((ck * 16u) ^ rxor));
                const float* bp = bx_s + part * 64 + j * 8;
                float2 f0 = __half22float2(*reinterpret_cast<const __half2*>(&v.x));
                float2 f1 = __half22float2(*reinterpret_cast<const __half2*>(&v.y));
                float2 f2 = __half22float2(*reinterpret_cast<const __half2*>(&v.z));
                float2 f3 = __half22float2(*reinterpret_cast<const __half2*>(&v.w));
                p = fmaf(f0.x, bp[0], p); p = fmaf(f0.y, bp[1], p);
                p = fmaf(f1.x, bp[2], p); p = fmaf(f1.y, bp[3], p);
                p = fmaf(f2.x, bp[4], p); p = fmaf(f2.y, bp[5], p);
                p = fmaf(f3.x, bp[6], p); p = fmaf(f3.y, bp[7], p);
            }
        } else {
            const int seg = part - 4;  // 0..3, 64 h-values each
            const float4* hseg = reinterpret_cast<const float4*>(h0_s + seg * 64);
            float any = 0.0f;
#pragma unroll
            for (int k = 0; k < 16; k++) {
                float4 hv = hseg[k];
                any += fabsf(hv.x) + fabsf(hv.y) + fabsf(hv.z) + fabsf(hv.w);
            }
            if (any != 0.0f) {
                const float4* a = reinterpret_cast<const float4*>(
                    WG + (size_t)(s * 256 + m0 + mm) * 512 + 256 + seg * 64);
#pragma unroll
                for (int k = 0; k < 16; k++) {
                    float4 av = a[k], hv = hseg[k];
                    p += av.x * hv.x + av.y * hv.y + av.z * hv.z + av.w * hv.w;
                }
            }
        }
        red[part * 64 + mm] = p;
        __syncthreads();
        if (tid < 64) {
            float b = bG[s * 256 + m0 + tid];
#pragma unroll
            for (int j = 0; j < 8; j++) {
                b += red[j * 64 + tid];
            }
            g_bias[gate][s][m0 + tid] = b;
        }
    }
}

// ---------------------------------------------------------------------------
// Kernel 2: main LSTM step (validated R12/R15 config: mma.sync fp16 1-pass
// GEMM; persistent over m-octants, mbarrier-pipelined B buffers; fp32 epilogue)
// grid = (token-tiles=128, 1, stream=8) = 1024 CTAs, block = 256 (8 warps)
// ---------------------------------------------------------------------------
#define SM_AH   0u
#define SM_BB   16384u     // buffer p at SM_BB + p*16384
#define SM_BIAS 49152u     // 1024 floats
#define SM_C0   53248u     // 256 floats
#define SM_MB   54272u     // full0, full1, rd0, rd1 (8B each)
#define SM_SZ   54304u

__global__ __launch_bounds__(256, 2)
void lstm_mma_kernel(const float* __restrict__ mod,
                     const float* __restrict__ c0,
                     float* __restrict__ out) {
    extern __shared__ char sm[];
    char* smp = sm;
    const uint32_t smbase = smem_u32(sm);

    const int s   = blockIdx.z;
    const int n0  = blockIdx.x * 128; // token base
    const int tid = threadIdx.x;

    const uint32_t mb_full[2] = {smbase + SM_MB, smbase + SM_MB + 8};
    const uint32_t mb_rd[2]   = {smbase + SM_MB + 16, smbase + SM_MB + 24};

    if (tid == 0) {
        MBAR_INIT(mb_full[0], 256);
        MBAR_INIT(mb_full[1], 256);
        MBAR_INIT(mb_rd[0], 256);
        MBAR_INIT(mb_rd[1], 256);
    }
    __syncthreads();

    // ---- kick off B[0] via cp.async into buffer 0, tracked by full[0] ----
    for (int c = tid; c < 1024; c += 256) {
        int r = c >> 3, ck = c & 7;
        int g = r >> 5, ml = r & 31;
        uint32_t off = swz((uint32_t)r, (uint32_t)ck * 16);
        CP_ASYNC16(smbase + SM_BB + off,
                   __cvta_generic_to_global(&g_wf16[g][s][ml][ck * 8]));
    }
    CP_ASYNC_MBAR_ARRIVE_NOINC(mb_full[0]);

    // ---- stage A (tokens): fp32 -> fp16, SW128 (overlaps B0 copy) ----
    for (int c = tid; c < 1024; c += 256) {
        int row = c >> 3, ck = c & 7;  // 16B chunk = 8 fp16
        const float* src = mod + (size_t)(n0 + row) * (SS * II) + s * II + ck * 8;
        uint4 v = cvt8_f32_to_h2(src);
        uint32_t off = swz((uint32_t)row, (uint32_t)ck * 16);
        *reinterpret_cast<uint4*>(smp + SM_AH + off) = v;
    }

    // ---- stage biases + c0 into smem ----
    for (int i = tid; i < 1024; i += 256) {
        int g = i >> 8, m = i & 255;
        *reinterpret_cast<float*>(smp + SM_BIAS + i * 4) = g_bias[g][s][m];
    }
    *reinterpret_cast<float*>(smp + SM_C0 + tid * 4) = c0[s * 256 + tid];
    __syncthreads();  // A + bias/c0 visible CTA-wide

    // ---- warp/lane geometry ----
    const int w    = tid >> 5;
    const int lane = tid & 31;
    const int wr   = w >> 1;  // token row group (0..3)
    const int wc   = w & 1;   // m column group (0..1)
    const int lrow  = lane & 15;
    const int lcolb = (lane >> 4) * 16;

    const uint32_t arow0 = (uint32_t)(wr * 32 + lrow);
    const uint32_t arow1 = (uint32_t)(wr * 32 + 16 + lrow);
    const uint32_t arb0 = arow0 * 128, arx0 = (arow0 & 7) << 4;
    const uint32_t arb1 = arow1 * 128, arx1 = (arow1 & 7) << 4;
    uint32_t brb[4], brx[4];
#pragma unroll
    for (int g = 0; g < 4; g++) {
        uint32_t brr = (uint32_t)(g * 32 + wc * 16) + (uint32_t)lrow;
        brb[g] = brr * 128;
        brx[g] = (brr & 7) << 4;
    }
    const uint32_t abh = smbase + SM_AH;

    const int qrow = lane >> 2, qcol = lane & 3;
    const float* bias_s = reinterpret_cast<const float*>(smp + SM_BIAS);
    const float* c0_s   = reinterpret_cast<const float*>(smp + SM_C0);

#pragma unroll 1
    for (int mq = 0; mq < 8; mq++) {
        const int p = mq & 1;
        const uint32_t bb = smbase + SM_BB + (uint32_t)p * 16384u;

        // wait B[mq] data ready
        MBAR_WAIT_PARITY(mb_full[p], (uint32_t)((mq >> 1) & 1));

        float acc[2][4][2][4];  // [token-tile][gate][n-half][frag]
#pragma unroll
        for (int mt = 0; mt < 2; mt++) {
#pragma unroll
            for (int g = 0; g < 4; g++) {
#pragma unroll
                for (int h = 0; h < 2; h++) {
#pragma unroll
                    for (int q = 0; q < 4; q++) {
                        acc[mt][g][h][q] = 0.0f;
                    }
                }
            }
        }

        // ---- 1-pass fp16 mainloop ----
#pragma unroll
        for (int k = 0; k < 4; k++) {
            const uint32_t kc = (uint32_t)lcolb + (uint32_t)k * 32;
            uint32_t a0[4], a1[4];
            ldsm4(a0[0], a0[1], a0[2], a0[3], abh + arb0 + (kc ^ arx0));
            ldsm4(a1[0], a1[1], a1[2], a1[3], abh + arb1 + (kc ^ arx1));
#pragma unroll
            for (int gp = 0; gp < 2; gp++) {
                uint32_t bh[2][4];
#pragma unroll
                for (int g2 = 0; g2 < 2; g2++) {
                    int g = gp * 2 + g2;
                    ldsm4(bh[g2][0], bh[g2][1], bh[g2][2], bh[g2][3],
                          bb + brb[g] + (kc ^ brx[g]));
                }
#pragma unroll
                for (int g2 = 0; g2 < 2; g2++) {
                    int g = gp * 2 + g2;
                    mma16816(acc[0][g][0], a0, bh[g2][0], bh[g2][2]);
                    mma16816(acc[0][g][1], a0, bh[g2][1], bh[g2][3]);
                    mma16816(acc[1][g][0], a1, bh[g2][0], bh[g2][2]);
                    mma16816(acc[1][g][1], a1, bh[g2][1], bh[g2][3]);
                }
            }
        }

        // release B buffer p (reads done for this warp)
        MBAR_ARRIVE(mb_rd[p]);

        // prefetch B[mq+1] into the other buffer (overlaps other warps' work)
        if (mq < 7) {
            const int np = 1 - p;
            const int mn = mq + 1;
            if (mq >= 1) {
                // wait until all warps finished reading buffer np at iteration mq-1
                MBAR_WAIT_PARITY(mb_rd[np], (uint32_t)((((mq + 1) >> 1) - 1) & 1));
            }
            const uint32_t bufb = smbase + SM_BB + (uint32_t)np * 16384u;
            for (int c = tid; c < 1024; c += 256) {
                int r = c >> 3, ck = c & 7;
                int g = r >> 5, ml = r & 31;
                uint32_t off = swz((uint32_t)r, (uint32_t)ck * 16);
                CP_ASYNC16(bufb + off,
                           __cvta_generic_to_global(&g_wf16[g][s][mn * 32 + ml][ck * 8]));
            }
            CP_ASYNC_MBAR_ARRIVE_NOINC(mb_full[np]);
        }

        // ---- fp32 epilogue (all 4 gates live in this thread's registers) ----
        const int mbase = mq * 32 + wc * 16;

        float bia[4][2][2];  // [gate][n-half][cp]
        float c0v[2][2];
#pragma unroll
        for (int h = 0; h < 2; h++) {
#pragma unroll
            for (int cp = 0; cp < 2; cp++) {
                int m = mbase + h * 8 + qcol * 2 + cp;
#pragma unroll
                for (int g = 0; g < 4; g++) {
                    bia[g][h][cp] = bias_s[g * 256 + m];
                }
                c0v[h][cp] = c0_s[m];
            }
        }

#pragma unroll
        for (int mt = 0; mt < 2; mt++) {
#pragma unroll
            for (int rp = 0; rp < 2; rp++) {
                int token = n0 + wr * 32 + mt * 16 + qrow + rp * 8;
#pragma unroll
                for (int h = 0; h < 2; h++) {
                    float hv0, hv1;
#pragma unroll
                    for (int cp = 0; cp < 2; cp++) {
                        int idx = rp * 2 + cp;
                        float iv = sigmoid_f(acc[mt][0][h][idx] + bia[0][h][cp]);
                        float fv = sigmoid_f(acc[mt][1][h][idx] + bia[1][h][cp]);
                        float gv = tanh_f(acc[mt][2][h][idx] + bia[2][h][cp]);
                        float ov = sigmoid_f(acc[mt][3][h][idx] + bia[3][h][cp]);
                        float cc = fmaf(fv, c0v[h][cp], iv * gv);
                        float hh = ov * tanh_f(cc);
                        if (cp == 0) { hv0 = hh; } else { hv1 = hh; }
                    }
                    float2 hv;
                    hv.x = hv0;
                    hv.y = hv1;
                    *reinterpret_cast<float2*>(
                        out + (size_t)token * (SS * MM) + s * 256 + mbase + h * 8 + qcol * 2) = hv;
                }
            }
        }
    }
}

// ---------------------------------------------------------------------------
// launch
// ---------------------------------------------------------------------------
extern "C" void kernel_launch(void* const* d_in, const int* in_sizes, int n_in,
                              void* d_out, int out_size) {
    const float* mod = (const float*)d_in[0];
    const float* h0  = (const float*)d_in[1];
    const float* c0  = (const float*)d_in[2];
    const float* Wx  = (const float*)d_in[3];
    const float* bx  = (const float*)d_in[4];
    const float* Wi  = (const float*)d_in[5];
    const float* bi  = (const float*)d_in[6];
    const float* Wf  = (const float*)d_in[7];
    const float* bf  = (const float*)d_in[8];
    const float* Wg  = (const float*)d_in[9];
    const float* bg  = (const float*)d_in[10];
    const float* Wo  = (const float*)d_in[11];
    const float* bo  = (const float*)d_in[12];
    float* out = (float*)d_out;

    cudaFuncSetAttribute(precompute_kernel,
                         cudaFuncAttributeMaxDynamicSharedMemorySize, PC_SZ);
    cudaFuncSetAttribute(lstm_mma_kernel,
                         cudaFuncAttributeMaxDynamicSharedMemorySize, SM_SZ);

    precompute_kernel<<<dim3(SS, 4, 4), 512, PC_SZ>>>(
        Wx, bx, Wi, bi, Wf, bf, Wg, bg, Wo, bo, h0);

    lstm_mma_kernel<<<dim3(NTOK / 128, 1, SS), 256, SM_SZ>>>(mod, c0, out);
}